// round 1
// baseline (speedup 1.0000x reference)
#include <cuda_runtime.h>

// Problem constants
#define B_    16
#define CIN   512
#define COUT  512
#define LSEQ  4096
#define SDIM  512
#define KW    3
#define EPS_  1e-8f

// Tiling
#define BM       128
#define BN       128
#define KC       16
#define BNP      (BN + 4)     // 130 used cols (halo) + pad
#define NTHREADS 256

// Scratch (device globals: no allocation allowed)
__device__ float d_s[B_ * CIN];            // modulation s[b,i]
__device__ float d_g[B_ * COUT];           // scale * demod[b,o]
__device__ float d_wsq[COUT * CIN];        // sum_k w[o,i,k]^2
__device__ float d_wt[KW * CIN * COUT];    // weight transposed [k][i][o]

// ---- packed f32x2 helpers (Blackwell dual fp32) ----
__device__ __forceinline__ unsigned long long dup2(float v) {
    unsigned long long r;
    asm("mov.b64 %0, {%1, %1};" : "=l"(r) : "f"(v));
    return r;
}
__device__ __forceinline__ void fma2(unsigned long long& d,
                                     unsigned long long a,
                                     unsigned long long b) {
    asm("fma.rn.f32x2 %0, %1, %2, %3;" : "=l"(d) : "l"(a), "l"(b), "l"(d));
}

// ---- prep kernel 1: s[b,i] = style[b,:] @ mod_w[i,:] + mod_b[i] ----
__global__ void k_style(const float* __restrict__ style,
                        const float* __restrict__ mod_w,
                        const float* __restrict__ mod_b) {
    int b = blockIdx.x, i = threadIdx.x;
    __shared__ float st[SDIM];
    st[i] = style[b * SDIM + i];
    __syncthreads();
    const float* wr = mod_w + i * SDIM;
    float acc = 0.f;
#pragma unroll 8
    for (int d = 0; d < SDIM; ++d) acc = fmaf(wr[d], st[d], acc);
    d_s[b * CIN + i] = acc + mod_b[i];
}

// ---- prep kernel 2: weight transpose + per-(o,i) squared sums ----
__global__ void k_wprep(const float* __restrict__ weight) {
    int idx = blockIdx.x * 256 + threadIdx.x;   // idx = i*COUT + o
    int i = idx >> 9;          // / COUT
    int o = idx & (COUT - 1);
    const float* wp = weight + (o * CIN + i) * KW;
    float w0 = wp[0], w1 = wp[1], w2 = wp[2];
    d_wsq[o * CIN + i] = w0 * w0 + w1 * w1 + w2 * w2;
    d_wt[(0 * CIN + i) * COUT + o] = w0;
    d_wt[(1 * CIN + i) * COUT + o] = w1;
    d_wt[(2 * CIN + i) * COUT + o] = w2;
}

// ---- prep kernel 3: g[b,o] = scale * rsqrt(scale^2 * sum_i wsq[o,i]*s[b,i]^2 + eps) ----
__global__ void k_demod() {
    int b = blockIdx.x, o = threadIdx.x;
    __shared__ float s2[CIN];
    float sv = d_s[b * CIN + o];      // thread idx doubles as staging index i
    s2[o] = sv * sv;
    __syncthreads();
    const float* wq = d_wsq + o * CIN;
    float acc = 0.f;
#pragma unroll 8
    for (int i = 0; i < CIN; ++i) acc = fmaf(wq[i], s2[i], acc);
    const float scale2 = 1.0f / (float)(CIN * KW * KW);  // scale^2, fan_in = cin*k*k
    float t = fmaf(scale2, acc, EPS_);
    d_g[b * COUT + o] = sqrtf(scale2) * rsqrtf(t);
}

// ---- main conv kernel: per-batch C[o,l] = sum_k W_k @ X_shift_k, epilogue g*acc+bias ----
__global__ void __launch_bounds__(NTHREADS, 2)
k_conv(const float* __restrict__ x,
       const float* __restrict__ bias,
       float* __restrict__ out) {
    extern __shared__ float smem[];
    float* sW = smem;                         // [2][3*KC*BM]
    float* sX = smem + 2 * 3 * KC * BM;       // [2][KC*BNP]

    const int tid = threadIdx.x;
    const int l0 = blockIdx.x * BN;
    const int o0 = blockIdx.y * BM;
    const int b  = blockIdx.z;
    const int tx = tid & 15;       // N direction, 16 threads, stride-16 columns
    const int ty = tid >> 4;       // M direction, 16 threads, 8 rows each

    const float* xb = x + (long)b * CIN * LSEQ;
    const float* sb = d_s + b * CIN;

    unsigned long long acc[4][8];
#pragma unroll
    for (int p = 0; p < 4; ++p)
#pragma unroll
        for (int j = 0; j < 8; ++j) acc[p][j] = 0ull;

    // stage loader: W tile [3][KC][BM] (coalesced from d_wt) + X tile [KC][130] with halo,
    // modulated by s[b,i] on the fly.
    auto load_stage = [&](int it, int buf) {
        const int i0 = it * KC;
        float* sWb = sW + buf * (3 * KC * BM);
        float* sXb = sX + buf * (KC * BNP);
#pragma unroll
        for (int r = 0; r < (3 * KC * BM) / NTHREADS; ++r) {   // 24 iters
            int idx = r * NTHREADS + tid;
            int ki = idx >> 7;            // / BM
            int o  = idx & (BM - 1);
            int k  = ki >> 4;             // / KC
            int i  = ki & (KC - 1);
            sWb[idx] = d_wt[(k * CIN + i0 + i) * COUT + o0 + o];
        }
#pragma unroll
        for (int r = 0; r < 9; ++r) {                          // KC*BNP = 2112
            int idx = r * NTHREADS + tid;
            if (idx < KC * BNP) {
                int i = idx / BNP;
                int c = idx - i * BNP;
                int gl = l0 - 1 + c;
                float v = 0.f;
                if (c < BN + 2 && gl >= 0 && gl < LSEQ)
                    v = xb[(i0 + i) * LSEQ + gl] * sb[i0 + i];
                sXb[idx] = v;
            }
        }
    };

    load_stage(0, 0);
    __syncthreads();

    const int NIT = CIN / KC;   // 32
    for (int it = 0; it < NIT; ++it) {
        const int cur = it & 1;
        if (it + 1 < NIT) load_stage(it + 1, cur ^ 1);

        const float* sWb = sW + cur * (3 * KC * BM);
        const float* sXb = sX + cur * (KC * BNP);

#pragma unroll 4
        for (int i = 0; i < KC; ++i) {
#pragma unroll
            for (int k = 0; k < 3; ++k) {
                const float* ap = sWb + (k * KC + i) * BM + ty * 8;
                unsigned long long a0 = *(const unsigned long long*)(ap + 0);
                unsigned long long a1 = *(const unsigned long long*)(ap + 2);
                unsigned long long a2 = *(const unsigned long long*)(ap + 4);
                unsigned long long a3 = *(const unsigned long long*)(ap + 6);
                const float* bp = sXb + i * BNP + tx + k;
#pragma unroll
                for (int j = 0; j < 8; ++j) {
                    unsigned long long bb = dup2(bp[16 * j]);
                    fma2(acc[0][j], a0, bb);
                    fma2(acc[1][j], a1, bb);
                    fma2(acc[2][j], a2, bb);
                    fma2(acc[3][j], a3, bb);
                }
            }
        }
        __syncthreads();
    }

    // epilogue: out = g[b,o]*acc + bias[o]
    const int gbase = b * COUT + o0;
#pragma unroll
    for (int p = 0; p < 4; ++p) {
        int m0 = ty * 8 + p * 2;
        float g0 = d_g[gbase + m0];
        float g1 = d_g[gbase + m0 + 1];
        float bi0 = bias[o0 + m0];
        float bi1 = bias[o0 + m0 + 1];
        float* op0 = out + ((long)(b * COUT + o0 + m0)) * LSEQ + l0 + tx;
        float* op1 = op0 + LSEQ;
#pragma unroll
        for (int j = 0; j < 8; ++j) {
            float2 v = *reinterpret_cast<float2*>(&acc[p][j]);
            op0[16 * j] = fmaf(g0, v.x, bi0);
            op1[16 * j] = fmaf(g1, v.y, bi1);
        }
    }
}

extern "C" void kernel_launch(void* const* d_in, const int* in_sizes, int n_in,
                              void* d_out, int out_size) {
    const float* input  = (const float*)d_in[0];
    const float* style  = (const float*)d_in[1];
    const float* weight = (const float*)d_in[2];
    const float* bias   = (const float*)d_in[3];
    const float* mod_w  = (const float*)d_in[4];
    const float* mod_b  = (const float*)d_in[5];
    float* out = (float*)d_out;

    k_style<<<B_, SDIM>>>(style, mod_w, mod_b);
    k_wprep<<<(CIN * COUT) / 256, 256>>>(weight);
    k_demod<<<B_, COUT>>>();

    size_t shmem = (size_t)(2 * 3 * KC * BM + 2 * KC * BNP) * sizeof(float);  // 66048 B
    cudaFuncSetAttribute(k_conv, cudaFuncAttributeMaxDynamicSharedMemorySize, (int)shmem);
    dim3 grid(LSEQ / BN, COUT / BM, B_);
    k_conv<<<grid, NTHREADS, shmem>>>(input, bias, out);
}

// round 3
// speedup vs baseline: 1.9031x; 1.9031x over previous
#include <cuda_runtime.h>
#include <cuda_bf16.h>
#include <cstdint>

// ---------------- problem constants ----------------
#define B_    16
#define CIN   512
#define COUT  512
#define LSEQ  4096
#define SDIM  512
#define KW    3
#define EPS_  1e-8f

// ---------------- GEMM tiling ----------------
#define MT      128                 // M tile (output channels)
#define NT      256                 // N tile (sequence positions)
#define KC      32                  // K per stage
#define KTOT    (KW * CIN)          // 1536 folded K
#define NSTG    (KTOT / KC)         // 48 stages
#define THREADS 512
#define ROWB    80                  // smem row stride bytes (32 bf16 + 16B pad)

// stage smem offsets (bytes)
#define SA_HI 0
#define SA_LO (MT * ROWB)                   // 10240
#define SB_HI (2 * MT * ROWB)               // 20480
#define SB_LO (2 * MT * ROWB + NT * ROWB)   // 40960
#define STG_BYTES (2 * MT * ROWB + 2 * NT * ROWB)   // 61440
#define SMEM_TOTAL (3 * STG_BYTES)                  // 184320

// ---------------- device scratch ----------------
__device__ float d_s[B_ * CIN];
__device__ float d_g[B_ * COUT];
__device__ float d_wsq[COUT * CIN];
__device__ __nv_bfloat16 d_ahi[(size_t)B_ * COUT * KTOT];   // A' hi [b][o][i']
__device__ __nv_bfloat16 d_alo[(size_t)B_ * COUT * KTOT];   // A' lo
__device__ __nv_bfloat16 d_xhi[(size_t)B_ * LSEQ * CIN];    // X^T hi [b][l][i]
__device__ __nv_bfloat16 d_xlo[(size_t)B_ * LSEQ * CIN];    // X^T lo

// ---------------- PTX helpers ----------------
__device__ __forceinline__ uint32_t smem_u32(const void* p) {
    uint32_t a;
    asm("{ .reg .u64 t; cvta.to.shared.u64 t, %1; cvt.u32.u64 %0, t; }" : "=r"(a) : "l"(p));
    return a;
}
__device__ __forceinline__ void cp16(uint32_t dst, const void* src, bool pred) {
    int sz = pred ? 16 : 0;
    asm volatile("cp.async.cg.shared.global [%0], [%1], 16, %2;" :: "r"(dst), "l"(src), "r"(sz));
}
#define CP_COMMIT() asm volatile("cp.async.commit_group;" ::: "memory")
#define CP_WAIT2()  asm volatile("cp.async.wait_group 2;" ::: "memory")
#define CP_WAIT0()  asm volatile("cp.async.wait_group 0;" ::: "memory")

__device__ __forceinline__ void ldsm4(uint32_t* r, uint32_t addr) {
    asm volatile("ldmatrix.sync.aligned.m8n8.x4.shared.b16 {%0,%1,%2,%3}, [%4];"
                 : "=r"(r[0]), "=r"(r[1]), "=r"(r[2]), "=r"(r[3]) : "r"(addr));
}
__device__ __forceinline__ void mma_bf16(float* c, const uint32_t* a, const uint32_t* b) {
    asm volatile(
        "mma.sync.aligned.m16n8k16.row.col.f32.bf16.bf16.f32 "
        "{%0,%1,%2,%3}, {%4,%5,%6,%7}, {%8,%9}, {%0,%1,%2,%3};"
        : "+f"(c[0]), "+f"(c[1]), "+f"(c[2]), "+f"(c[3])
        : "r"(a[0]), "r"(a[1]), "r"(a[2]), "r"(a[3]), "r"(b[0]), "r"(b[1]));
}

// ================= prep kernels =================
__global__ void k_style(const float* __restrict__ style,
                        const float* __restrict__ mod_w,
                        const float* __restrict__ mod_b) {
    int b = blockIdx.x, i = threadIdx.x;
    __shared__ float st[SDIM];
    st[i] = style[b * SDIM + i];
    __syncthreads();
    const float* wr = mod_w + i * SDIM;
    float acc = 0.f;
#pragma unroll 8
    for (int d = 0; d < SDIM; ++d) acc = fmaf(wr[d], st[d], acc);
    d_s[b * CIN + i] = acc + mod_b[i];
}

__global__ void k_wsq(const float* __restrict__ weight) {
    int idx = blockIdx.x * 256 + threadIdx.x;
    int i = idx >> 9, o = idx & (COUT - 1);
    const float* wp = weight + (o * CIN + i) * KW;
    float w0 = wp[0], w1 = wp[1], w2 = wp[2];
    d_wsq[o * CIN + i] = w0 * w0 + w1 * w1 + w2 * w2;
}

__global__ void k_demod() {
    int b = blockIdx.x, o = threadIdx.x;
    __shared__ float s2[CIN];
    float sv = d_s[b * CIN + o];
    s2[o] = sv * sv;
    __syncthreads();
    const float* wq = d_wsq + o * CIN;
    float acc = 0.f;
#pragma unroll 8
    for (int i = 0; i < CIN; ++i) acc = fmaf(wq[i], s2[i], acc);
    const float scale2 = 1.0f / (float)(CIN * KW * KW);
    d_g[b * COUT + o] = sqrtf(scale2) * rsqrtf(fmaf(scale2, acc, EPS_));
}

// A'[b][o][k*512+i] = w[o,i,k] * s[b,i], split hi/lo bf16
__global__ void k_aprep(const float* __restrict__ weight) {
    int b = blockIdx.y, o = blockIdx.x;
    const float* sb = d_s + b * CIN;
    size_t obase = ((size_t)b * COUT + o) * KTOT;
    for (int idx = threadIdx.x; idx < KTOT; idx += 256) {
        int k = idx >> 9, i = idx & 511;
        float v = weight[(o * CIN + i) * KW + k] * sb[i];
        __nv_bfloat16 hi = __float2bfloat16_rn(v);
        __nv_bfloat16 lo = __float2bfloat16_rn(v - __bfloat162float(hi));
        d_ahi[obase + idx] = hi;
        d_alo[obase + idx] = lo;
    }
}

// X^T[b][l][i] = x[b][i][l], split hi/lo bf16
__global__ void k_xprep(const float* __restrict__ x) {
    __shared__ float t[64][33];
    int b = blockIdx.z, i0 = blockIdx.y * 64, l0 = blockIdx.x * 32;
    int tx = threadIdx.x, ty = threadIdx.y;   // (32, 8)
#pragma unroll
    for (int rr = 0; rr < 8; ++rr) {
        int r = rr * 8 + ty;
        t[r][tx] = x[((size_t)b * CIN + i0 + r) * LSEQ + l0 + tx];
    }
    __syncthreads();
#pragma unroll
    for (int w = 0; w < 4; ++w) {
        int r = w * 8 + ty;
        float v0 = t[2 * tx][r], v1 = t[2 * tx + 1][r];
        __nv_bfloat16 h0 = __float2bfloat16_rn(v0);
        __nv_bfloat16 h1 = __float2bfloat16_rn(v1);
        __nv_bfloat16 g0 = __float2bfloat16_rn(v0 - __bfloat162float(h0));
        __nv_bfloat16 g1 = __float2bfloat16_rn(v1 - __bfloat162float(h1));
        size_t idx = ((size_t)b * LSEQ + l0 + r) * CIN + i0 + 2 * tx;
        uint32_t ph = (uint32_t)*(uint16_t*)&h0 | ((uint32_t)*(uint16_t*)&h1 << 16);
        uint32_t pl = (uint32_t)*(uint16_t*)&g0 | ((uint32_t)*(uint16_t*)&g1 << 16);
        *(uint32_t*)(d_xhi + idx) = ph;
        *(uint32_t*)(d_xlo + idx) = pl;
    }
}

// ================= main GEMM (mma.sync bf16, 3-product split) =================
__global__ void __launch_bounds__(THREADS, 1)
k_gemm(const float* __restrict__ bias, float* __restrict__ out) {
    extern __shared__ char smem[];
    const uint32_t sm = smem_u32(smem);
    const int tid = threadIdx.x;
    const int wid = tid >> 5, lane = tid & 31;
    const int wm = wid & 3, wn = wid >> 2;           // 4 x 4 warp grid
    const int l0 = blockIdx.x * NT, o0 = blockIdx.y * MT, b = blockIdx.z;

    // ---- stage loader ----
    auto load_stage = [&](int st, int buf) {
        const uint32_t sbase = sm + buf * STG_BYTES;
        const int tap = st >> 4;                     // 0..2
        const int ic = (st & 15) * KC;               // k offset within CIN
        {   // A: 128 rows x 4 chunks = 512 -> one per thread (hi & lo)
            int r = tid >> 2, c = tid & 3;
            size_t go = (((size_t)b * COUT + o0 + r) * KTOT + st * KC) * 2 + c * 16;
            uint32_t dst = sbase + r * ROWB + c * 16;
            cp16(dst + SA_HI, (const char*)d_ahi + go, true);
            cp16(dst + SA_LO, (const char*)d_alo + go, true);
        }
#pragma unroll
        for (int j = 0; j < 2; ++j) {   // B: 256 rows x 4 chunks = 1024 -> two per thread
            int idx = j * THREADS + tid;
            int r = idx >> 2, c = idx & 3;
            int y = l0 + r + tap - 1;
            bool ok = (unsigned)y < (unsigned)LSEQ;
            int ys = ok ? y : 0;
            size_t go = ((size_t)b * LSEQ + ys) * CIN * 2 + ic * 2 + c * 16;
            uint32_t dst = sbase + r * ROWB + c * 16;
            cp16(dst + SB_HI, (const char*)d_xhi + go, ok);
            cp16(dst + SB_LO, (const char*)d_xlo + go, ok);
        }
    };

    // ---- per-lane ldmatrix base addresses (within a stage buffer) ----
    // A: x4 matrices (m0-7,k0-7),(m8-15,k0-7),(m0-7,k8-15),(m8-15,k8-15)
    const uint32_t aOff = (uint32_t)((wm * 32 + (lane & 15)) * ROWB + (lane >> 4) * 16);
    // B: x4 matrices (n0-7,k0-7),(n0-7,k8-15),(n8-15,k0-7),(n8-15,k8-15)
    const uint32_t bOff = (uint32_t)((wn * 64 + (lane & 7) + ((lane >> 4) & 1) * 8) * ROWB +
                                     ((lane >> 3) & 1) * 16);

    float acc[2][8][4];
#pragma unroll
    for (int mt = 0; mt < 2; ++mt)
#pragma unroll
        for (int nt = 0; nt < 8; ++nt)
#pragma unroll
            for (int e = 0; e < 4; ++e) acc[mt][nt][e] = 0.f;

    load_stage(0, 0); CP_COMMIT();
    load_stage(1, 1); CP_COMMIT();
    load_stage(2, 2); CP_COMMIT();

    for (int st = 0; st < NSTG; ++st) {
        const int buf = st - (st / 3) * 3;
        CP_WAIT2();
        __syncthreads();

        const uint32_t sbase = sm + buf * STG_BYTES;
        uint32_t ah[2][4], al[2][4], bb[4][4];
#pragma unroll
        for (int s16 = 0; s16 < 2; ++s16) {
            const uint32_t ks = s16 * 32;
            ldsm4(ah[0], sbase + SA_HI + aOff + ks);
            ldsm4(ah[1], sbase + SA_HI + aOff + 16 * ROWB + ks);
            ldsm4(al[0], sbase + SA_LO + aOff + ks);
            ldsm4(al[1], sbase + SA_LO + aOff + 16 * ROWB + ks);
#pragma unroll
            for (int nq = 0; nq < 4; ++nq)
                ldsm4(bb[nq], sbase + SB_HI + bOff + nq * 16 * ROWB + ks);
#pragma unroll
            for (int nq = 0; nq < 4; ++nq) {
#pragma unroll
                for (int h = 0; h < 2; ++h) {
                    uint32_t bf[2] = { bb[nq][2 * h], bb[nq][2 * h + 1] };
                    int nt = nq * 2 + h;
                    mma_bf16(acc[0][nt], ah[0], bf);   // Ahi*Bhi
                    mma_bf16(acc[1][nt], ah[1], bf);
                    mma_bf16(acc[0][nt], al[0], bf);   // Alo*Bhi
                    mma_bf16(acc[1][nt], al[1], bf);
                }
            }
#pragma unroll
            for (int nq = 0; nq < 4; ++nq)
                ldsm4(bb[nq], sbase + SB_LO + bOff + nq * 16 * ROWB + ks);
#pragma unroll
            for (int nq = 0; nq < 4; ++nq) {
#pragma unroll
                for (int h = 0; h < 2; ++h) {
                    uint32_t bf[2] = { bb[nq][2 * h], bb[nq][2 * h + 1] };
                    int nt = nq * 2 + h;
                    mma_bf16(acc[0][nt], ah[0], bf);   // Ahi*Blo
                    mma_bf16(acc[1][nt], ah[1], bf);
                }
            }
        }
        __syncthreads();
        if (st + 3 < NSTG) load_stage(st + 3, buf);
        CP_COMMIT();
    }
    CP_WAIT0();

    // ---- epilogue: out = g[b,o]*acc + bias[o] ----
    const int q = lane >> 2, rr = lane & 3;
#pragma unroll
    for (int mt = 0; mt < 2; ++mt) {
#pragma unroll
        for (int half = 0; half < 2; ++half) {
            int o = o0 + wm * 32 + mt * 16 + q + half * 8;
            float g = d_g[b * COUT + o];
            float bs = bias[o];
            float* op = out + ((size_t)b * COUT + o) * LSEQ + l0 + wn * 64 + rr * 2;
#pragma unroll
            for (int nt = 0; nt < 8; ++nt) {
                float2 v;
                v.x = fmaf(g, acc[mt][nt][2 * half + 0], bs);
                v.y = fmaf(g, acc[mt][nt][2 * half + 1], bs);
                *(float2*)(op + nt * 8) = v;
            }
        }
    }
}

// ================= host launcher =================
extern "C" void kernel_launch(void* const* d_in, const int* in_sizes, int n_in,
                              void* d_out, int out_size) {
    const float* input  = (const float*)d_in[0];
    const float* style  = (const float*)d_in[1];
    const float* weight = (const float*)d_in[2];
    const float* bias   = (const float*)d_in[3];
    const float* mod_w  = (const float*)d_in[4];
    const float* mod_b  = (const float*)d_in[5];
    float* out = (float*)d_out;

    k_style<<<B_, SDIM>>>(style, mod_w, mod_b);
    k_wsq<<<(CIN * COUT) / 256, 256>>>(weight);
    k_demod<<<B_, COUT>>>();
    {
        dim3 g(COUT, B_);
        k_aprep<<<g, 256>>>(weight);
    }
    {
        dim3 g(LSEQ / 32, CIN / 64, B_);
        dim3 t(32, 8);
        k_xprep<<<g, t>>>(input);
    }
    cudaFuncSetAttribute(k_gemm, cudaFuncAttributeMaxDynamicSharedMemorySize, SMEM_TOTAL);
    dim3 grid(LSEQ / NT, COUT / MT, B_);
    k_gemm<<<grid, THREADS, SMEM_TOTAL>>>(bias, out);
}

// round 4
// speedup vs baseline: 3.3174x; 1.7432x over previous
#include <cuda_runtime.h>
#include <cuda_fp16.h>
#include <cstdint>

// ---------------- problem constants ----------------
#define B_    16
#define CIN   512
#define COUT  512
#define LSEQ  4096
#define SDIM  512
#define KW    3
#define EPS_  1e-8f

// ---------------- GEMM tiling ----------------
#define MT      128                 // M tile (output channels)
#define NT      256                 // N tile (sequence positions)
#define KC      32                  // K per stage
#define KTOT    (KW * CIN)          // 1536 folded K
#define NSTG    (KTOT / KC)         // 48 stages
#define THREADS 256
#define ROWB    80                  // smem row stride (64B data + 16B pad)

// stage smem offsets (bytes)
#define SA 0
#define SB (MT * ROWB)                      // 10240
#define STG_BYTES ((MT + NT) * ROWB)        // 30720
#define SMEM_TOTAL (3 * STG_BYTES)          // 92160

// ---------------- device scratch ----------------
__device__ float d_s[B_ * CIN];
__device__ float d_g[B_ * COUT];
__device__ float d_wsq[COUT * CIN];
__device__ __half d_a[(size_t)B_ * COUT * KTOT];    // A' [b][o][i'] = w*s, fp16
__device__ __half d_xt[(size_t)B_ * LSEQ * CIN];    // X^T [b][l][i], fp16

// ---------------- PTX helpers ----------------
__device__ __forceinline__ uint32_t smem_u32(const void* p) {
    uint32_t a;
    asm("{ .reg .u64 t; cvta.to.shared.u64 t, %1; cvt.u32.u64 %0, t; }" : "=r"(a) : "l"(p));
    return a;
}
__device__ __forceinline__ void cp16(uint32_t dst, const void* src, bool pred) {
    int sz = pred ? 16 : 0;
    asm volatile("cp.async.cg.shared.global [%0], [%1], 16, %2;" :: "r"(dst), "l"(src), "r"(sz));
}
#define CP_COMMIT() asm volatile("cp.async.commit_group;" ::: "memory")
#define CP_WAIT2()  asm volatile("cp.async.wait_group 2;" ::: "memory")
#define CP_WAIT0()  asm volatile("cp.async.wait_group 0;" ::: "memory")

__device__ __forceinline__ void ldsm4(uint32_t* r, uint32_t addr) {
    asm volatile("ldmatrix.sync.aligned.m8n8.x4.shared.b16 {%0,%1,%2,%3}, [%4];"
                 : "=r"(r[0]), "=r"(r[1]), "=r"(r[2]), "=r"(r[3]) : "r"(addr));
}
__device__ __forceinline__ void mma_fp16(float* c, const uint32_t* a, const uint32_t* b) {
    asm volatile(
        "mma.sync.aligned.m16n8k16.row.col.f32.f16.f16.f32 "
        "{%0,%1,%2,%3}, {%4,%5,%6,%7}, {%8,%9}, {%0,%1,%2,%3};"
        : "+f"(c[0]), "+f"(c[1]), "+f"(c[2]), "+f"(c[3])
        : "r"(a[0]), "r"(a[1]), "r"(a[2]), "r"(a[3]), "r"(b[0]), "r"(b[1]));
}

// ================= prep kernels =================
__global__ void k_style(const float* __restrict__ style,
                        const float* __restrict__ mod_w,
                        const float* __restrict__ mod_b) {
    int b = blockIdx.x, i = threadIdx.x;
    __shared__ float st[SDIM];
    st[i] = style[b * SDIM + i];
    __syncthreads();
    const float* wr = mod_w + i * SDIM;
    float acc = 0.f;
#pragma unroll 8
    for (int d = 0; d < SDIM; ++d) acc = fmaf(wr[d], st[d], acc);
    d_s[b * CIN + i] = acc + mod_b[i];
}

__global__ void k_wsq(const float* __restrict__ weight) {
    int idx = blockIdx.x * 256 + threadIdx.x;
    int i = idx >> 9, o = idx & (COUT - 1);
    const float* wp = weight + (o * CIN + i) * KW;
    float w0 = wp[0], w1 = wp[1], w2 = wp[2];
    d_wsq[o * CIN + i] = w0 * w0 + w1 * w1 + w2 * w2;
}

__global__ void k_demod() {
    int b = blockIdx.x, o = threadIdx.x;
    __shared__ float s2[CIN];
    float sv = d_s[b * CIN + o];
    s2[o] = sv * sv;
    __syncthreads();
    const float* wq = d_wsq + o * CIN;
    float acc = 0.f;
#pragma unroll 8
    for (int i = 0; i < CIN; ++i) acc = fmaf(wq[i], s2[i], acc);
    const float scale2 = 1.0f / (float)(CIN * KW * KW);
    d_g[b * COUT + o] = sqrtf(scale2) * rsqrtf(fmaf(scale2, acc, EPS_));
}

// A'[b][o][k*512+i] = w[o,i,k] * s[b,i] in fp16
__global__ void k_aprep(const float* __restrict__ weight) {
    int b = blockIdx.y, o = blockIdx.x;
    const float* sb = d_s + b * CIN;
    size_t obase = ((size_t)b * COUT + o) * KTOT;
    for (int idx = threadIdx.x; idx < KTOT; idx += 256) {
        int k = idx >> 9, i = idx & 511;
        d_a[obase + idx] = __float2half_rn(weight[(o * CIN + i) * KW + k] * sb[i]);
    }
}

// X^T[b][l][i] = x[b][i][l] in fp16
__global__ void k_xprep(const float* __restrict__ x) {
    __shared__ float t[64][33];
    int b = blockIdx.z, i0 = blockIdx.y * 64, l0 = blockIdx.x * 32;
    int tx = threadIdx.x, ty = threadIdx.y;   // (32, 8)
#pragma unroll
    for (int rr = 0; rr < 8; ++rr) {
        int r = rr * 8 + ty;
        t[r][tx] = x[((size_t)b * CIN + i0 + r) * LSEQ + l0 + tx];
    }
    __syncthreads();
#pragma unroll
    for (int w = 0; w < 4; ++w) {
        int r = w * 8 + ty;
        __half h0 = __float2half_rn(t[2 * tx][r]);
        __half h1 = __float2half_rn(t[2 * tx + 1][r]);
        size_t idx = ((size_t)b * LSEQ + l0 + r) * CIN + i0 + 2 * tx;
        uint32_t ph = (uint32_t)*(uint16_t*)&h0 | ((uint32_t)*(uint16_t*)&h1 << 16);
        *(uint32_t*)(d_xt + idx) = ph;
    }
}

// ================= main GEMM (single fp16 product) =================
__global__ void __launch_bounds__(THREADS, 1)
k_gemm(const float* __restrict__ bias, float* __restrict__ out) {
    extern __shared__ char smem[];
    const uint32_t sm = smem_u32(smem);
    const int tid = threadIdx.x;
    const int wid = tid >> 5, lane = tid & 31;
    const int wm = wid & 1, wn = wid >> 1;          // 2 x 4 warp grid, warp tile 64x64
    const int l0 = blockIdx.x * NT, o0 = blockIdx.y * MT, b = blockIdx.z;

    // ---- stage loader: A 128 rows + B 256 rows, 4 x 16B chunks per row ----
    auto load_stage = [&](int st, int buf) {
        const uint32_t sbase = sm + buf * STG_BYTES;
        const int tap = st >> 4;                    // 0..2
        const int ic = (st & 15) * KC;
#pragma unroll
        for (int j = 0; j < 2; ++j) {               // A: 512 chunks
            int idx = j * THREADS + tid;
            int r = idx >> 2, c = idx & 3;
            size_t go = (((size_t)b * COUT + o0 + r) * KTOT + st * KC) * 2 + c * 16;
            cp16(sbase + SA + r * ROWB + c * 16, (const char*)d_a + go, true);
        }
#pragma unroll
        for (int j = 0; j < 4; ++j) {               // B: 1024 chunks
            int idx = j * THREADS + tid;
            int r = idx >> 2, c = idx & 3;
            int y = l0 + r + tap - 1;
            bool ok = (unsigned)y < (unsigned)LSEQ;
            int ys = ok ? y : 0;
            size_t go = ((size_t)b * LSEQ + ys) * CIN * 2 + ic * 2 + c * 16;
            cp16(sbase + SB + r * ROWB + c * 16, (const char*)d_xt + go, ok);
        }
    };

    // ldmatrix lane address offsets
    const uint32_t aOff = (uint32_t)((wm * 64 + (lane & 15)) * ROWB + (lane >> 4) * 16);
    const uint32_t bOff = (uint32_t)((wn * 64 + (lane & 7) + ((lane >> 4) & 1) * 8) * ROWB +
                                     ((lane >> 3) & 1) * 16);

    float acc[4][8][4];
#pragma unroll
    for (int f = 0; f < 4; ++f)
#pragma unroll
        for (int nt = 0; nt < 8; ++nt)
#pragma unroll
            for (int e = 0; e < 4; ++e) acc[f][nt][e] = 0.f;

    load_stage(0, 0); CP_COMMIT();
    load_stage(1, 1); CP_COMMIT();
    load_stage(2, 2); CP_COMMIT();

    for (int st = 0; st < NSTG; ++st) {
        const int buf = st - (st / 3) * 3;
        CP_WAIT2();
        __syncthreads();

        const uint32_t sbase = sm + buf * STG_BYTES;
#pragma unroll
        for (int s16 = 0; s16 < 2; ++s16) {
            const uint32_t ks = s16 * 32;
            uint32_t af[4][4], bb[4][4];
#pragma unroll
            for (int f = 0; f < 4; ++f)
                ldsm4(af[f], sbase + SA + aOff + f * 16 * ROWB + ks);
#pragma unroll
            for (int nq = 0; nq < 4; ++nq)
                ldsm4(bb[nq], sbase + SB + bOff + nq * 16 * ROWB + ks);
#pragma unroll
            for (int f = 0; f < 4; ++f)
#pragma unroll
                for (int nq = 0; nq < 4; ++nq)
#pragma unroll
                    for (int h = 0; h < 2; ++h) {
                        uint32_t bf[2] = { bb[nq][2 * h], bb[nq][2 * h + 1] };
                        mma_fp16(acc[f][nq * 2 + h], af[f], bf);
                    }
        }
        __syncthreads();
        if (st + 3 < NSTG) load_stage(st + 3, buf);
        CP_COMMIT();
    }
    CP_WAIT0();

    // ---- epilogue: out = g[b,o]*acc + bias[o] ----
    const int q = lane >> 2, rr = lane & 3;
#pragma unroll
    for (int f = 0; f < 4; ++f) {
#pragma unroll
        for (int half = 0; half < 2; ++half) {
            int o = o0 + wm * 64 + f * 16 + q + half * 8;
            float g = d_g[b * COUT + o];
            float bs = bias[o];
            float* op = out + ((size_t)b * COUT + o) * LSEQ + l0 + wn * 64 + rr * 2;
#pragma unroll
            for (int nt = 0; nt < 8; ++nt) {
                float2 v;
                v.x = fmaf(g, acc[f][nt][2 * half + 0], bs);
                v.y = fmaf(g, acc[f][nt][2 * half + 1], bs);
                *(float2*)(op + nt * 8) = v;
            }
        }
    }
}

// ================= host launcher =================
extern "C" void kernel_launch(void* const* d_in, const int* in_sizes, int n_in,
                              void* d_out, int out_size) {
    const float* input  = (const float*)d_in[0];
    const float* style  = (const float*)d_in[1];
    const float* weight = (const float*)d_in[2];
    const float* bias   = (const float*)d_in[3];
    const float* mod_w  = (const float*)d_in[4];
    const float* mod_b  = (const float*)d_in[5];
    float* out = (float*)d_out;

    k_style<<<B_, SDIM>>>(style, mod_w, mod_b);
    k_wsq<<<(CIN * COUT) / 256, 256>>>(weight);
    k_demod<<<B_, COUT>>>();
    {
        dim3 g(COUT, B_);
        k_aprep<<<g, 256>>>(weight);
    }
    {
        dim3 g(LSEQ / 32, CIN / 64, B_);
        dim3 t(32, 8);
        k_xprep<<<g, t>>>(input);
    }
    cudaFuncSetAttribute(k_gemm, cudaFuncAttributeMaxDynamicSharedMemorySize, SMEM_TOTAL);
    dim3 grid(LSEQ / NT, COUT / MT, B_);
    k_gemm<<<grid, THREADS, SMEM_TOTAL>>>(bias, out);
}